// round 16
// baseline (speedup 1.0000x reference)
#include <cuda_runtime.h>

// CubePadding: x [B=4, 6, C=64, H=128, W=128] f32 -> out [B, 6, C, 132, 132] f32
// FINAL — measured-best kernel (30.4-30.9us kernel time across 7 runs;
// dur_us modal 35.328). Single kernel; boundary (halo gather) and interior
// (streaming copy) blocks interleaved in groups of 353 (97 boundary + 256
// interior, exact x24) so the DRAM read/write mix stays uniform end-to-end.
// Interior: warp-per-4-rows (MLP=4), shuffle-realigned aligned float4
// streaming stores; default-policy loads (boundary gathers hit L2 on freshly
// streamed rows). 8 blocks/SM.
// 208 MB compulsory traffic / ~30.6us = ~6.8 TB/s effective (~85% of HBM
// spec): at the practical mixed read/write DRAM roofline. All structural
// alternatives (split kernels, 8-row warps, smem+TMA bulk stores, ld/st cache
// policies) measured and rejected in rounds 1-15.

#define Pp 2
#define Bn 4
#define Cn 64
#define Hn 128
#define Wn 128
#define OH 132
#define OW 132

#define NG        (Bn * 6 * Cn)               // 1536 face-channels
#define ROWS_PER_WARP 4
#define INT_WARPS (NG * Hn / ROWS_PER_WARP)   // 49152
#define INT_BLOCKS (INT_WARPS / 8)            // 6144
#define BND_PER_G (4 * 33 + Hn * 2)           // 388 boundary float4s per g
#define BND_TOTAL (NG * BND_PER_G)            // 595968 (= 2328 * 256 exactly)
#define BND_BLOCKS (BND_TOTAL / 256)          // 2328
#define GRP_BND   97
#define GRP_INT   256
#define GRP_SIZE  (GRP_BND + GRP_INT)         // 353
#define TOTAL_BLOCKS (INT_BLOCKS + BND_BLOCKS) // 8472 = 24 * 353

// face ids: 0=back(fb) 1=down(fd) 2=front(ff) 3=left(fl) 4=right(fr) 5=top(ft)

__device__ __forceinline__ void top_map(int f, int i, int j, int& sf, int& sh, int& sw) {
    switch (f) {
        case 0: sf = 5; sh = Pp - 1 - i;  sw = j;           break;
        case 1: sf = 2; sh = Hn - Pp + i; sw = j;           break;
        case 2: sf = 5; sh = Hn - Pp + i; sw = j;           break;
        case 3: sf = 5; sh = j;           sw = i;           break;
        case 4: sf = 5; sh = j;           sw = Wn - 1 - i;  break;
        default: sf = 0; sh = Pp - 1 - i; sw = j;           break;
    }
}

__device__ __forceinline__ void bot_map(int f, int i, int j, int& sf, int& sh, int& sw) {
    switch (f) {
        case 0: sf = 1; sh = Hn - 1 - i;  sw = j;           break;
        case 1: sf = 0; sh = Hn - 1 - i;  sw = j;           break;
        case 2: sf = 1; sh = i;           sw = j;           break;
        case 3: sf = 1; sh = j;           sw = Pp - 1 - i;  break;
        case 4: sf = 1; sh = j;           sw = Wn - Pp + i; break;
        default: sf = 2; sh = i;          sw = j;           break;
    }
}

__device__ __forceinline__ void lft_map(int f, int r, int i, int& sf, int& sh, int& sw) {
    switch (f) {
        case 0: sf = 4; sh = r;           sw = Wn - Pp + i; break;
        case 1: sf = 3; sh = Hn - 1 - i;  sw = r;           break;
        case 2: sf = 3; sh = r;           sw = Wn - Pp + i; break;
        case 3: sf = 0; sh = r;           sw = Wn - Pp + i; break;
        case 4: sf = 2; sh = r;           sw = Wn - Pp + i; break;
        default: sf = 3; sh = i;          sw = r;           break;
    }
}

__device__ __forceinline__ void rgt_map(int f, int r, int i, int& sf, int& sh, int& sw) {
    switch (f) {
        case 0: sf = 3; sh = r;           sw = i;           break;
        case 1: sf = 4; sh = Hn - Pp + i; sw = r;           break;
        case 2: sf = 4; sh = r;           sw = i;           break;
        case 3: sf = 2; sh = r;           sw = i;           break;
        case 4: sf = 0; sh = r;           sw = i;           break;
        default: sf = 4; sh = Pp - 1 - i; sw = r;           break;
    }
}

__device__ __forceinline__ void src_map(int f, int ho, int wo, int& sf, int& sh, int& sw) {
    if (wo >= Pp && wo < Pp + Wn) {
        int j = wo - Pp;
        if (ho < Pp)                top_map(f, ho, j, sf, sh, sw);
        else if (ho >= Pp + Hn)     bot_map(f, ho - Pp - Hn, j, sf, sh, sw);
        else { sf = f; sh = ho - Pp; sw = j; }
    } else if (wo < Pp) {
        if (ho < Pp)                top_map(f, ho, 0, sf, sh, sw);
        else if (ho >= Pp + Hn)     bot_map(f, ho - Pp - Hn, 0, sf, sh, sw);
        else                        lft_map(f, ho - Pp, wo, sf, sh, sw);
    } else {
        if (ho < Pp)                top_map(f, ho, Wn - 1, sf, sh, sw);
        else if (ho >= Pp + Hn)     bot_map(f, ho - Pp - Hn, Wn - 1, sf, sh, sw);
        else                        rgt_map(f, ho - Pp, wo - Pp - Wn, sf, sh, sw);
    }
}

__device__ __forceinline__ float gather1(const float* __restrict__ x,
                                         int b, int f, int c, int ho, int wo) {
    int sf, sh, sw;
    src_map(f, ho, wo, sf, sh, sw);
    return __ldg(x + ((size_t)((b * 6 + sf) * Cn + c)) * (Hn * Wn) + sh * Wn + sw);
}

__global__ void __launch_bounds__(256, 8)
cube_pad(const float* __restrict__ x, float4* __restrict__ out4) {
    unsigned grp = blockIdx.x / GRP_SIZE;
    unsigned r   = blockIdx.x - grp * GRP_SIZE;

    if (r >= GRP_BND) {
        // ---------------- interior: warp-per-4-rows ----------------
        unsigned iblk = grp * GRP_INT + (r - GRP_BND);           // < INT_BLOCKS
        unsigned warp = threadIdx.x >> 5;
        unsigned lane = threadIdx.x & 31;
        unsigned idx  = iblk * 8u + warp;                        // < INT_WARPS
        unsigned g    = idx >> 5;                                // 32 row-quads per g
        unsigned h0   = (idx & 31u) * ROWS_PER_WARP;

        const float4* src4 = (const float4*)(x + ((size_t)g << 14)) + h0 * (Wn / 4) + lane;
        float4 a0 = __ldg(src4);
        float4 a1 = __ldg(src4 + 32);
        float4 a2 = __ldg(src4 + 64);
        float4 a3 = __ldg(src4 + 96);

        float4* dst = out4 + (size_t)g * (OH * 33) + (h0 + Pp) * 33 + (lane + 1);

        float nx, ny;
        nx = __shfl_down_sync(0xffffffffu, a0.x, 1);
        ny = __shfl_down_sync(0xffffffffu, a0.y, 1);
        if (lane < 31) __stcs(dst,      make_float4(a0.z, a0.w, nx, ny));
        nx = __shfl_down_sync(0xffffffffu, a1.x, 1);
        ny = __shfl_down_sync(0xffffffffu, a1.y, 1);
        if (lane < 31) __stcs(dst + 33, make_float4(a1.z, a1.w, nx, ny));
        nx = __shfl_down_sync(0xffffffffu, a2.x, 1);
        ny = __shfl_down_sync(0xffffffffu, a2.y, 1);
        if (lane < 31) __stcs(dst + 66, make_float4(a2.z, a2.w, nx, ny));
        nx = __shfl_down_sync(0xffffffffu, a3.x, 1);
        ny = __shfl_down_sync(0xffffffffu, a3.y, 1);
        if (lane < 31) __stcs(dst + 99, make_float4(a3.z, a3.w, nx, ny));
        return;
    }

    // ---------------- boundary: per-float4 gather ----------------
    unsigned bblk = grp * GRP_BND + r;                           // < BND_BLOCKS
    unsigned bt = bblk * 256u + threadIdx.x;
    if (bt >= BND_TOTAL) return;

    unsigned g = bt / BND_PER_G;
    unsigned k = bt - g * BND_PER_G;

    int ho, w4;
    if (k < 132) {                      // full rows ho in {0,1,130,131}
        unsigned rr = k / 33u;
        w4 = k - rr * 33u;
        ho = (rr < 2) ? (int)rr : (int)(rr + 128);
    } else {                            // interior rows, edge float4s (w4 0 / 32)
        unsigned k2 = k - 132;
        ho = (int)(k2 >> 1) + Pp;
        w4 = (k2 & 1) ? 32 : 0;
    }

    int b_ = g / (6 * Cn);
    int f  = (g / Cn) % 6;
    int c  = g % Cn;
    int wo = w4 * 4;

    float4 v;
    v.x = gather1(x, b_, f, c, ho, wo + 0);
    v.y = gather1(x, b_, f, c, ho, wo + 1);
    v.z = gather1(x, b_, f, c, ho, wo + 2);
    v.w = gather1(x, b_, f, c, ho, wo + 3);

    out4[(size_t)g * (OH * 33) + ho * 33 + w4] = v;
}

extern "C" void kernel_launch(void* const* d_in, const int* in_sizes, int n_in,
                              void* d_out, int out_size) {
    const float* x = (const float*)d_in[0];
    cube_pad<<<TOTAL_BLOCKS, 256>>>(x, (float4*)d_out);
}

// round 17
// speedup vs baseline: 1.0009x; 1.0009x over previous
#include <cuda_runtime.h>

// CubePadding: x [B=4, 6, C=64, H=128, W=128] f32 -> out [B, 6, C, 132, 132] f32
// FINAL — converged. Measured 30.4-31.1us kernel / 35.328us modal dur across
// 8 runs. Single kernel; boundary (halo gather) and interior (streaming copy)
// blocks interleaved in groups of 353 (97 boundary + 256 interior, exact x24)
// so the DRAM read/write mix stays uniform end-to-end. Interior:
// warp-per-4-rows (MLP=4), shuffle-realigned aligned float4 streaming stores;
// default-policy loads (boundary gathers hit L2 on freshly streamed rows).
// 8 blocks/SM.
// 208 MB compulsory traffic at ~6.8 TB/s effective (~85% of HBM spec): at the
// practical mixed read/write DRAM roofline. All alternatives (split kernels,
// 8-row warps, smem+TMA bulk stores, ld/st cache policies) measured and
// rejected in rounds 1-16. 1.67x over the first passing kernel.

#define Pp 2
#define Bn 4
#define Cn 64
#define Hn 128
#define Wn 128
#define OH 132
#define OW 132

#define NG        (Bn * 6 * Cn)               // 1536 face-channels
#define ROWS_PER_WARP 4
#define INT_WARPS (NG * Hn / ROWS_PER_WARP)   // 49152
#define INT_BLOCKS (INT_WARPS / 8)            // 6144
#define BND_PER_G (4 * 33 + Hn * 2)           // 388 boundary float4s per g
#define BND_TOTAL (NG * BND_PER_G)            // 595968 (= 2328 * 256 exactly)
#define BND_BLOCKS (BND_TOTAL / 256)          // 2328
#define GRP_BND   97
#define GRP_INT   256
#define GRP_SIZE  (GRP_BND + GRP_INT)         // 353
#define TOTAL_BLOCKS (INT_BLOCKS + BND_BLOCKS) // 8472 = 24 * 353

// face ids: 0=back(fb) 1=down(fd) 2=front(ff) 3=left(fl) 4=right(fr) 5=top(ft)

__device__ __forceinline__ void top_map(int f, int i, int j, int& sf, int& sh, int& sw) {
    switch (f) {
        case 0: sf = 5; sh = Pp - 1 - i;  sw = j;           break;
        case 1: sf = 2; sh = Hn - Pp + i; sw = j;           break;
        case 2: sf = 5; sh = Hn - Pp + i; sw = j;           break;
        case 3: sf = 5; sh = j;           sw = i;           break;
        case 4: sf = 5; sh = j;           sw = Wn - 1 - i;  break;
        default: sf = 0; sh = Pp - 1 - i; sw = j;           break;
    }
}

__device__ __forceinline__ void bot_map(int f, int i, int j, int& sf, int& sh, int& sw) {
    switch (f) {
        case 0: sf = 1; sh = Hn - 1 - i;  sw = j;           break;
        case 1: sf = 0; sh = Hn - 1 - i;  sw = j;           break;
        case 2: sf = 1; sh = i;           sw = j;           break;
        case 3: sf = 1; sh = j;           sw = Pp - 1 - i;  break;
        case 4: sf = 1; sh = j;           sw = Wn - Pp + i; break;
        default: sf = 2; sh = i;          sw = j;           break;
    }
}

__device__ __forceinline__ void lft_map(int f, int r, int i, int& sf, int& sh, int& sw) {
    switch (f) {
        case 0: sf = 4; sh = r;           sw = Wn - Pp + i; break;
        case 1: sf = 3; sh = Hn - 1 - i;  sw = r;           break;
        case 2: sf = 3; sh = r;           sw = Wn - Pp + i; break;
        case 3: sf = 0; sh = r;           sw = Wn - Pp + i; break;
        case 4: sf = 2; sh = r;           sw = Wn - Pp + i; break;
        default: sf = 3; sh = i;          sw = r;           break;
    }
}

__device__ __forceinline__ void rgt_map(int f, int r, int i, int& sf, int& sh, int& sw) {
    switch (f) {
        case 0: sf = 3; sh = r;           sw = i;           break;
        case 1: sf = 4; sh = Hn - Pp + i; sw = r;           break;
        case 2: sf = 4; sh = r;           sw = i;           break;
        case 3: sf = 2; sh = r;           sw = i;           break;
        case 4: sf = 0; sh = r;           sw = i;           break;
        default: sf = 4; sh = Pp - 1 - i; sw = r;           break;
    }
}

__device__ __forceinline__ void src_map(int f, int ho, int wo, int& sf, int& sh, int& sw) {
    if (wo >= Pp && wo < Pp + Wn) {
        int j = wo - Pp;
        if (ho < Pp)                top_map(f, ho, j, sf, sh, sw);
        else if (ho >= Pp + Hn)     bot_map(f, ho - Pp - Hn, j, sf, sh, sw);
        else { sf = f; sh = ho - Pp; sw = j; }
    } else if (wo < Pp) {
        if (ho < Pp)                top_map(f, ho, 0, sf, sh, sw);
        else if (ho >= Pp + Hn)     bot_map(f, ho - Pp - Hn, 0, sf, sh, sw);
        else                        lft_map(f, ho - Pp, wo, sf, sh, sw);
    } else {
        if (ho < Pp)                top_map(f, ho, Wn - 1, sf, sh, sw);
        else if (ho >= Pp + Hn)     bot_map(f, ho - Pp - Hn, Wn - 1, sf, sh, sw);
        else                        rgt_map(f, ho - Pp, wo - Pp - Wn, sf, sh, sw);
    }
}

__device__ __forceinline__ float gather1(const float* __restrict__ x,
                                         int b, int f, int c, int ho, int wo) {
    int sf, sh, sw;
    src_map(f, ho, wo, sf, sh, sw);
    return __ldg(x + ((size_t)((b * 6 + sf) * Cn + c)) * (Hn * Wn) + sh * Wn + sw);
}

__global__ void __launch_bounds__(256, 8)
cube_pad(const float* __restrict__ x, float4* __restrict__ out4) {
    unsigned grp = blockIdx.x / GRP_SIZE;
    unsigned r   = blockIdx.x - grp * GRP_SIZE;

    if (r >= GRP_BND) {
        // ---------------- interior: warp-per-4-rows ----------------
        unsigned iblk = grp * GRP_INT + (r - GRP_BND);           // < INT_BLOCKS
        unsigned warp = threadIdx.x >> 5;
        unsigned lane = threadIdx.x & 31;
        unsigned idx  = iblk * 8u + warp;                        // < INT_WARPS
        unsigned g    = idx >> 5;                                // 32 row-quads per g
        unsigned h0   = (idx & 31u) * ROWS_PER_WARP;

        const float4* src4 = (const float4*)(x + ((size_t)g << 14)) + h0 * (Wn / 4) + lane;
        float4 a0 = __ldg(src4);
        float4 a1 = __ldg(src4 + 32);
        float4 a2 = __ldg(src4 + 64);
        float4 a3 = __ldg(src4 + 96);

        float4* dst = out4 + (size_t)g * (OH * 33) + (h0 + Pp) * 33 + (lane + 1);

        float nx, ny;
        nx = __shfl_down_sync(0xffffffffu, a0.x, 1);
        ny = __shfl_down_sync(0xffffffffu, a0.y, 1);
        if (lane < 31) __stcs(dst,      make_float4(a0.z, a0.w, nx, ny));
        nx = __shfl_down_sync(0xffffffffu, a1.x, 1);
        ny = __shfl_down_sync(0xffffffffu, a1.y, 1);
        if (lane < 31) __stcs(dst + 33, make_float4(a1.z, a1.w, nx, ny));
        nx = __shfl_down_sync(0xffffffffu, a2.x, 1);
        ny = __shfl_down_sync(0xffffffffu, a2.y, 1);
        if (lane < 31) __stcs(dst + 66, make_float4(a2.z, a2.w, nx, ny));
        nx = __shfl_down_sync(0xffffffffu, a3.x, 1);
        ny = __shfl_down_sync(0xffffffffu, a3.y, 1);
        if (lane < 31) __stcs(dst + 99, make_float4(a3.z, a3.w, nx, ny));
        return;
    }

    // ---------------- boundary: per-float4 gather ----------------
    unsigned bblk = grp * GRP_BND + r;                           // < BND_BLOCKS
    unsigned bt = bblk * 256u + threadIdx.x;
    if (bt >= BND_TOTAL) return;

    unsigned g = bt / BND_PER_G;
    unsigned k = bt - g * BND_PER_G;

    int ho, w4;
    if (k < 132) {                      // full rows ho in {0,1,130,131}
        unsigned rr = k / 33u;
        w4 = k - rr * 33u;
        ho = (rr < 2) ? (int)rr : (int)(rr + 128);
    } else {                            // interior rows, edge float4s (w4 0 / 32)
        unsigned k2 = k - 132;
        ho = (int)(k2 >> 1) + Pp;
        w4 = (k2 & 1) ? 32 : 0;
    }

    int b_ = g / (6 * Cn);
    int f  = (g / Cn) % 6;
    int c  = g % Cn;
    int wo = w4 * 4;

    float4 v;
    v.x = gather1(x, b_, f, c, ho, wo + 0);
    v.y = gather1(x, b_, f, c, ho, wo + 1);
    v.z = gather1(x, b_, f, c, ho, wo + 2);
    v.w = gather1(x, b_, f, c, ho, wo + 3);

    out4[(size_t)g * (OH * 33) + ho * 33 + w4] = v;
}

extern "C" void kernel_launch(void* const* d_in, const int* in_sizes, int n_in,
                              void* d_out, int out_size) {
    const float* x = (const float*)d_in[0];
    cube_pad<<<TOTAL_BLOCKS, 256>>>(x, (float4*)d_out);
}